// round 8
// baseline (speedup 1.0000x reference)
#include <cuda_runtime.h>
#include <cuda_bf16.h>

// Problem geometry (fixed by the reference)
#define BB    4
#define NN    512
#define HH    12
#define DHD   64
#define HID   768
#define EE    65536
#define NRELV 64
#define BN_SEG (BB*NN)          // 2048 segments
#define SEGH  (BN_SEG*HH)       // 24576

// ---------------- scratch (static device memory; no allocs) ----------------
__device__ float    g_Q[BN_SEG*HID];
__device__ float    g_K[BN_SEG*HID];
__device__ float    g_V[BN_SEG*HID];
__device__ float    g_logits[EE*HH];     // reused to hold ex after pass 5
__device__ unsigned g_mkey[SEGH];
__device__ float    g_denom[SEGH];

// ---------------- init: zero output + softmax accumulators ----------------
__global__ void init_kernel(float* __restrict__ out, int n_out) {
    int i = blockIdx.x * blockDim.x + threadIdx.x;
    int stride = gridDim.x * blockDim.x;
    for (int j = i; j < n_out; j += stride) out[j] = 0.0f;
    for (int j = i; j < SEGH; j += stride) { g_mkey[j] = 0u; g_denom[j] = 0.0f; }
}

// ---------------- fused QKV projection: Y = X @ W^T + b (NT gemm) ----------
// M=2048, N=768, K=768. Tile 64x64x16, 256 threads, 4x4 per thread.
__global__ __launch_bounds__(256)
void gemm_qkv(const float* __restrict__ X,
              const float* __restrict__ Wq, const float* __restrict__ bq,
              const float* __restrict__ Wk, const float* __restrict__ bk,
              const float* __restrict__ Wv, const float* __restrict__ bv)
{
    const float* W; const float* bias; float* Y;
    if (blockIdx.z == 0)      { W = Wq; bias = bq; Y = g_Q; }
    else if (blockIdx.z == 1) { W = Wk; bias = bk; Y = g_K; }
    else                      { W = Wv; bias = bv; Y = g_V; }

    __shared__ float Xs[16][68];   // [k][m], padded stride 68 (16B-aligned rows)
    __shared__ float Ws[16][68];   // [k][n]

    int tid = threadIdx.x;
    int tx = tid & 15;             // n micro index
    int ty = tid >> 4;             // m micro index
    int m0 = blockIdx.y * 64;
    int n0 = blockIdx.x * 64;

    int lr = tid >> 2;             // 0..63: row within tile
    int lq = tid & 3;              // 0..3 : float4 slot within BK=16

    const float* Xp = X + (m0 + lr) * HID + lq * 4;
    const float* Wp = W + (n0 + lr) * HID + lq * 4;

    float acc[4][4];
    #pragma unroll
    for (int i = 0; i < 4; i++)
        #pragma unroll
        for (int j = 0; j < 4; j++) acc[i][j] = 0.0f;

    for (int k0 = 0; k0 < HID; k0 += 16) {
        float4 xv = *(const float4*)(Xp + k0);
        float4 wv = *(const float4*)(Wp + k0);
        Xs[lq*4+0][lr] = xv.x; Xs[lq*4+1][lr] = xv.y;
        Xs[lq*4+2][lr] = xv.z; Xs[lq*4+3][lr] = xv.w;
        Ws[lq*4+0][lr] = wv.x; Ws[lq*4+1][lr] = wv.y;
        Ws[lq*4+2][lr] = wv.z; Ws[lq*4+3][lr] = wv.w;
        __syncthreads();
        #pragma unroll
        for (int kk = 0; kk < 16; kk++) {
            float4 a = *(const float4*)&Xs[kk][ty*4];
            float4 b = *(const float4*)&Ws[kk][tx*4];
            acc[0][0] = fmaf(a.x, b.x, acc[0][0]); acc[0][1] = fmaf(a.x, b.y, acc[0][1]);
            acc[0][2] = fmaf(a.x, b.z, acc[0][2]); acc[0][3] = fmaf(a.x, b.w, acc[0][3]);
            acc[1][0] = fmaf(a.y, b.x, acc[1][0]); acc[1][1] = fmaf(a.y, b.y, acc[1][1]);
            acc[1][2] = fmaf(a.y, b.z, acc[1][2]); acc[1][3] = fmaf(a.y, b.w, acc[1][3]);
            acc[2][0] = fmaf(a.z, b.x, acc[2][0]); acc[2][1] = fmaf(a.z, b.y, acc[2][1]);
            acc[2][2] = fmaf(a.z, b.z, acc[2][2]); acc[2][3] = fmaf(a.z, b.w, acc[2][3]);
            acc[3][0] = fmaf(a.w, b.x, acc[3][0]); acc[3][1] = fmaf(a.w, b.y, acc[3][1]);
            acc[3][2] = fmaf(a.w, b.z, acc[3][2]); acc[3][3] = fmaf(a.w, b.w, acc[3][3]);
        }
        __syncthreads();
    }

    float4 bb = *(const float4*)&bias[n0 + tx*4];
    #pragma unroll
    for (int i = 0; i < 4; i++) {
        int row = m0 + ty*4 + i;
        float4 r;
        r.x = acc[i][0] + bb.x; r.y = acc[i][1] + bb.y;
        r.z = acc[i][2] + bb.z; r.w = acc[i][3] + bb.w;
        *(float4*)&Y[row * HID + n0 + tx*4] = r;
    }
}

// ---------------- per-edge logits: logits[e,h] = (Qe[h]·(Re))·Ke[h] / 8 ----
// One block per edge, 192 threads = 6 warps, warp handles 2 heads.
__global__ __launch_bounds__(192)
void edge_logits(const float* __restrict__ rel, const int* __restrict__ ei)
{
    int e  = blockIdx.x;
    int be = ei[e];
    int he = ei[EE + e];
    int te = ei[2*EE + e];
    int re = ei[3*EE + e];

    __shared__ float Re[64][68];   // [d][k], padded (row = 272B, 16B aligned)
    __shared__ float Qs[HH][65];   // [h][d]

    int tid = threadIdx.x;
    const float4* rp = (const float4*)(rel + (size_t)re * 4096);
    for (int j = tid; j < 1024; j += 192) {
        float4 v = rp[j];
        int d = j >> 4, kq = j & 15;
        *(float4*)&Re[d][kq*4] = v;
    }
    const float* qp = g_Q + (be * NN + he) * HID;
    for (int j = tid; j < HID; j += 192) Qs[j >> 6][j & 63] = qp[j];
    __syncthreads();

    int w    = tid >> 5;
    int lane = tid & 31;
    int h    = 2*w + (lane >> 4);   // 0..11
    int kq   = lane & 15;           // float4 index over k

    float4 acc = make_float4(0.f, 0.f, 0.f, 0.f);
    #pragma unroll
    for (int d = 0; d < 64; d++) {
        float  q  = Qs[h][d];
        float4 rv = *(const float4*)&Re[d][kq*4];
        acc.x = fmaf(q, rv.x, acc.x);
        acc.y = fmaf(q, rv.y, acc.y);
        acc.z = fmaf(q, rv.z, acc.z);
        acc.w = fmaf(q, rv.w, acc.w);
    }

    const float4* kp = (const float4*)(g_K + (be * NN + te) * HID + h * DHD);
    float4 kv = kp[kq];
    float s = acc.x*kv.x + acc.y*kv.y + acc.z*kv.z + acc.w*kv.w;
    s += __shfl_xor_sync(0xffffffffu, s, 8);
    s += __shfl_xor_sync(0xffffffffu, s, 4);
    s += __shfl_xor_sync(0xffffffffu, s, 2);
    s += __shfl_xor_sync(0xffffffffu, s, 1);
    if (kq == 0) g_logits[e * HH + h] = s * 0.125f;
}

// ---------------- segment max (encoded uint atomicMax) ---------------------
__device__ __forceinline__ unsigned f2key(float f) {
    unsigned b = __float_as_uint(f);
    return (b & 0x80000000u) ? ~b : (b | 0x80000000u);
}
__device__ __forceinline__ float key2f(unsigned k) {
    unsigned b = (k & 0x80000000u) ? (k & 0x7FFFFFFFu) : ~k;
    return __uint_as_float(b);
}

__global__ void seg_max(const int* __restrict__ ei) {
    int e = blockIdx.x * blockDim.x + threadIdx.x;
    if (e >= EE) return;
    int seg = ei[e] * NN + ei[EE + e];
    #pragma unroll
    for (int h = 0; h < HH; h++) {
        unsigned key = f2key(g_logits[e * HH + h]);
        atomicMax(&g_mkey[seg * HH + h], key);
    }
}

// ---------------- exp + segment sum ----------------------------------------
__global__ void seg_expsum(const int* __restrict__ ei) {
    int e = blockIdx.x * blockDim.x + threadIdx.x;
    if (e >= EE) return;
    int seg = ei[e] * NN + ei[EE + e];
    #pragma unroll
    for (int h = 0; h < HH; h++) {
        float m  = key2f(g_mkey[seg * HH + h]);
        float ex = expf(g_logits[e * HH + h] - m);
        g_logits[e * HH + h] = ex;                 // now holds ex
        atomicAdd(&g_denom[seg * HH + h], ex);
    }
}

// ---------------- aggregate: out[seg,h,:] += p * V[tail,h,:] ----------------
__device__ __forceinline__ void red_add_v4(float4* addr, float4 v) {
    asm volatile("red.global.add.v4.f32 [%0], {%1, %2, %3, %4};"
                 :: "l"(addr), "f"(v.x), "f"(v.y), "f"(v.z), "f"(v.w)
                 : "memory");
}

__global__ __launch_bounds__(256)
void aggregate(const int* __restrict__ ei, float* __restrict__ out)
{
    int e = blockIdx.x * 8 + (threadIdx.x >> 5);   // warp per edge
    int lane = threadIdx.x & 31;
    if (e >= EE) return;
    int be = ei[e];
    int he = ei[EE + e];
    int te = ei[2*EE + e];
    int seg = be * NN + he;

    const float4* vp = (const float4*)(g_V + (be * NN + te) * HID);
    float4* op = (float4*)out + (size_t)seg * 192;

    #pragma unroll
    for (int j = 0; j < 6; j++) {
        int flat = lane + 32 * j;                  // 0..191 -> (h, float4-in-head)
        int h = flat >> 4;
        float p = g_logits[e * HH + h] * __frcp_rn(g_denom[seg * HH + h]);
        float4 v = vp[flat];
        float4 r = make_float4(p*v.x, p*v.y, p*v.z, p*v.w);
        red_add_v4(&op[flat], r);
    }
}

// ---------------- launch ----------------------------------------------------
extern "C" void kernel_launch(void* const* d_in, const int* in_sizes, int n_in,
                              void* d_out, int out_size)
{
    const float* node_states = (const float*)d_in[0];
    const int*   edge_idx    = (const int*)  d_in[1];
    // d_in[2] node_type_ids: unused
    const float* Wq = (const float*)d_in[3];
    const float* bq = (const float*)d_in[4];
    const float* Wk = (const float*)d_in[5];
    const float* bk = (const float*)d_in[6];
    const float* Wv = (const float*)d_in[7];
    const float* bv = (const float*)d_in[8];
    const float* rel = (const float*)d_in[9];
    float* out = (float*)d_out;

    // 1. zero output + softmax accumulators
    init_kernel<<<2048, 256>>>(out, out_size);

    // 2. Q/K/V projections (z selects which projection)
    dim3 ggrid(HID / 64, BN_SEG / 64, 3);
    gemm_qkv<<<ggrid, 256>>>(node_states, Wq, bq, Wk, bk, Wv, bv);

    // 3. per-edge relation logits
    edge_logits<<<EE, 192>>>(rel, edge_idx);

    // 4. segment max
    seg_max<<<EE / 256, 256>>>(edge_idx);

    // 5. exp + segment sum
    seg_expsum<<<EE / 256, 256>>>(edge_idx);

    // 6. weighted aggregation into output
    aggregate<<<EE / 8, 256>>>(edge_idx, out);
}